// round 1
// baseline (speedup 1.0000x reference)
#include <cuda_runtime.h>
#include <cuda_bf16.h>
#include <math.h>

// ---------------- problem constants ----------------
#define BATCH   64
#define SEQ     197
#define TOK     (BATCH*SEQ)      // 12608
#define DIM     768
#define NHEAD   12
#define HDIM    64
#define HID     3072
#define BH      (BATCH*NHEAD)    // 768
#define LN_EPS  1e-6f

// ---------------- scratch (device globals; no allocation allowed) ----------------
__device__ float g_q  [(long)BH*SEQ*HDIM];   // [bh, s, d]
__device__ float g_kT [(long)BH*HDIM*SEQ];   // [bh, d, s]
__device__ float g_v  [(long)BH*SEQ*HDIM];   // [bh, s, d]
__device__ float g_sc [(long)BH*SEQ*SEQ];    // [bh, s, t]
__device__ float g_ctx[(long)TOK*DIM];       // [tok, dim]
__device__ float g_ao [(long)TOK*DIM];
__device__ float g_x1 [(long)TOK*DIM];
__device__ float g_h  [(long)TOK*HID];
__device__ float g_mlp[(long)TOK*DIM];

// ---------------- generic register-tiled SGEMM ----------------
// C = alpha*(A[M,K] @ B[K,N]) + bias[n], optional GELU, multiple output layouts.
// OUTMODE: 0 plain [z,M,N]; 1 head-q/v  [(b*H+h)*S+s, d]; 2 head-kT [(b*H+h)*HD+d, s];
//          3 ctx   [(b*S+m)*DIM + h*HD + n]  (z = b*H+h, m = s, n = d)
// EPI: 0 none, 1 exact GELU
template<int BM,int BN,int BK,int TM,int TN,int OUTMODE,int EPI>
__launch_bounds__((BM/TM)*(BN/TN))
__global__ void sgemm_k(const float* __restrict__ A, const float* __restrict__ Bw,
                        const float* __restrict__ bias, float* __restrict__ C,
                        int M, int N, int K, int lda, int ldb,
                        long strideA, long strideB, float alpha)
{
    constexpr int THREADS = (BM/TM)*(BN/TN);
    __shared__ float As[BK][BM+4];
    __shared__ float Bs[BK][BN];

    const int z = blockIdx.z;
    A  += (long)z * strideA;
    Bw += (long)z * strideB;

    const int tileM = blockIdx.y * BM;
    const int tileN = blockIdx.x * BN;
    const int tid   = threadIdx.x;
    const int tcol  = tid % (BN/TN);
    const int trow  = tid / (BN/TN);

    float acc[TM][TN];
    #pragma unroll
    for (int i=0;i<TM;i++)
        #pragma unroll
        for (int j=0;j<TN;j++) acc[i][j] = 0.f;

    float ra[TM], rb[TN];

    for (int k0 = 0; k0 < K; k0 += BK) {
        #pragma unroll
        for (int idx = tid; idx < BM*BK; idx += THREADS) {
            int mm = idx / BK, kk = idx % BK;
            int gm = tileM + mm, gk = k0 + kk;
            As[kk][mm] = (gm < M && gk < K) ? A[(long)gm*lda + gk] : 0.f;
        }
        #pragma unroll
        for (int idx = tid; idx < BK*BN; idx += THREADS) {
            int kk = idx / BN, nn = idx % BN;
            int gk = k0 + kk, gn = tileN + nn;
            Bs[kk][nn] = (gk < K && gn < N) ? Bw[(long)gk*ldb + gn] : 0.f;
        }
        __syncthreads();

        #pragma unroll
        for (int kk = 0; kk < BK; kk++) {
            #pragma unroll
            for (int i=0;i<TM;i++) ra[i] = As[kk][trow*TM+i];
            #pragma unroll
            for (int j=0;j<TN;j++) rb[j] = Bs[kk][tcol*TN+j];
            #pragma unroll
            for (int i=0;i<TM;i++)
                #pragma unroll
                for (int j=0;j<TN;j++)
                    acc[i][j] = fmaf(ra[i], rb[j], acc[i][j]);
        }
        __syncthreads();
    }

    #pragma unroll
    for (int i=0;i<TM;i++) {
        int gm = tileM + trow*TM + i;
        if (gm >= M) continue;
        int b = 0, s = 0;
        if (OUTMODE == 1 || OUTMODE == 2) { b = gm / SEQ; s = gm - b*SEQ; }
        #pragma unroll
        for (int j=0;j<TN;j++) {
            int gn = tileN + tcol*TN + j;
            if (gn >= N) continue;
            float val = acc[i][j] * alpha;
            if (bias) val += bias[gn];
            if (EPI == 1) val = 0.5f * val * (1.f + erff(val * 0.70710678118654752f));
            long idx;
            if (OUTMODE == 0) {
                idx = (long)z*M*N + (long)gm*N + gn;
            } else if (OUTMODE == 1) {       // q/v: [(b*H+h)*S+s, dd]
                int h = gn >> 6, dd = gn & 63;
                idx = (((long)(b*NHEAD + h))*SEQ + s)*HDIM + dd;
            } else if (OUTMODE == 2) {       // kT: [(b*H+h)*HD+dd, s]
                int h = gn >> 6, dd = gn & 63;
                idx = (((long)(b*NHEAD + h))*HDIM + dd)*SEQ + s;
            } else {                          // ctx: z=b*H+h, gm=s, gn=dd
                int bb = z / NHEAD, hh = z % NHEAD;
                idx = ((long)(bb*SEQ + gm))*DIM + hh*HDIM + gn;
            }
            C[idx] = val;
        }
    }
}

// ---------------- softmax: one warp per row of length 197 ----------------
__global__ void softmax_k(float* __restrict__ sc, int rows)
{
    int warp = (blockIdx.x * blockDim.x + threadIdx.x) >> 5;
    int lane = threadIdx.x & 31;
    if (warp >= rows) return;
    float* row = sc + (long)warp * SEQ;

    float v[7];
    float m = -1e30f;
    #pragma unroll
    for (int i=0;i<7;i++) {
        int c = lane + i*32;
        v[i] = (c < SEQ) ? row[c] : -1e30f;
        m = fmaxf(m, v[i]);
    }
    #pragma unroll
    for (int o=16;o;o>>=1) m = fmaxf(m, __shfl_xor_sync(0xffffffffu, m, o));

    float sum = 0.f;
    #pragma unroll
    for (int i=0;i<7;i++) { v[i] = __expf(v[i] - m); sum += v[i]; }
    #pragma unroll
    for (int o=16;o;o>>=1) sum += __shfl_xor_sync(0xffffffffu, sum, o);

    float inv = 1.f / sum;
    #pragma unroll
    for (int i=0;i<7;i++) {
        int c = lane + i*32;
        if (c < SEQ) row[c] = v[i]*inv;
    }
}

// ---------------- residual + LayerNorm: out = x + LN(y)*g + b ----------------
__global__ void add_ln_k(const float* __restrict__ x, const float* __restrict__ y,
                         const float* __restrict__ g, const float* __restrict__ be,
                         float* __restrict__ out)
{
    const int r = blockIdx.x;
    const float* yr = y + (long)r*DIM;
    const float* xr = x + (long)r*DIM;
    float* orow = out + (long)r*DIM;

    float s = 0.f, sq = 0.f;
    for (int i = threadIdx.x; i < DIM; i += blockDim.x) {
        float t = yr[i]; s += t; sq += t*t;
    }
    __shared__ float red[64];
    #pragma unroll
    for (int o=16;o;o>>=1) { s += __shfl_xor_sync(0xffffffffu, s, o); sq += __shfl_xor_sync(0xffffffffu, sq, o); }
    int w = threadIdx.x >> 5, lane = threadIdx.x & 31;
    if (lane == 0) { red[w] = s; red[w+32] = sq; }
    __syncthreads();
    if (threadIdx.x < 32) {
        int nw = blockDim.x >> 5;
        s  = (threadIdx.x < nw) ? red[threadIdx.x]      : 0.f;
        sq = (threadIdx.x < nw) ? red[threadIdx.x + 32] : 0.f;
        #pragma unroll
        for (int o=16;o;o>>=1) { s += __shfl_xor_sync(0xffffffffu, s, o); sq += __shfl_xor_sync(0xffffffffu, sq, o); }
        if (threadIdx.x == 0) { red[0] = s; red[1] = sq; }
    }
    __syncthreads();
    float mu   = red[0] * (1.f/DIM);
    float var  = red[1] * (1.f/DIM) - mu*mu;
    float rstd = rsqrtf(var + LN_EPS);
    for (int i = threadIdx.x; i < DIM; i += blockDim.x) {
        orow[i] = xr[i] + (yr[i] - mu) * rstd * g[i] + be[i];
    }
}

// ---------------- launch ----------------
extern "C" void kernel_launch(void* const* d_in, const int* in_sizes, int n_in,
                              void* d_out, int out_size)
{
    const float* x   = (const float*)d_in[0];
    const float* Wq  = (const float*)d_in[1];
    const float* bq  = (const float*)d_in[2];
    const float* Wk  = (const float*)d_in[3];
    const float* bk  = (const float*)d_in[4];
    const float* Wv  = (const float*)d_in[5];
    const float* bv  = (const float*)d_in[6];
    const float* Wo  = (const float*)d_in[7];
    const float* bo  = (const float*)d_in[8];
    const float* W1  = (const float*)d_in[9];
    const float* b1  = (const float*)d_in[10];
    const float* W2  = (const float*)d_in[11];
    const float* b2  = (const float*)d_in[12];
    const float* g1  = (const float*)d_in[13];
    const float* be1 = (const float*)d_in[14];
    const float* g2  = (const float*)d_in[15];
    const float* be2 = (const float*)d_in[16];
    float* out = (float*)d_out;

    float *q, *kT, *v, *sc, *ctx, *ao, *x1, *hh, *mlp;
    cudaGetSymbolAddress((void**)&q,   g_q);
    cudaGetSymbolAddress((void**)&kT,  g_kT);
    cudaGetSymbolAddress((void**)&v,   g_v);
    cudaGetSymbolAddress((void**)&sc,  g_sc);
    cudaGetSymbolAddress((void**)&ctx, g_ctx);
    cudaGetSymbolAddress((void**)&ao,  g_ao);
    cudaGetSymbolAddress((void**)&x1,  g_x1);
    cudaGetSymbolAddress((void**)&hh,  g_h);
    cudaGetSymbolAddress((void**)&mlp, g_mlp);

    const dim3 blk(256);
    const float one = 1.0f;
    const float scale = 0.125f;   // 1/sqrt(64)

    // --- QKV projections (fused head-layout epilogues) ---
    {
        dim3 grid(DIM/128, (TOK + 127)/128);
        sgemm_k<128,128,16,8,8,1,0><<<grid, blk>>>(x, Wq, bq, q,  TOK, DIM, DIM, DIM, DIM, 0, 0, one);
        sgemm_k<128,128,16,8,8,2,0><<<grid, blk>>>(x, Wk, bk, kT, TOK, DIM, DIM, DIM, DIM, 0, 0, one);
        sgemm_k<128,128,16,8,8,1,0><<<grid, blk>>>(x, Wv, bv, v,  TOK, DIM, DIM, DIM, DIM, 0, 0, one);
    }

    // --- scores = q @ kT * scale   (batched over 768 bh) ---
    {
        dim3 grid((SEQ+63)/64, (SEQ+63)/64, BH);
        sgemm_k<64,64,16,4,4,0,0><<<grid, blk>>>(q, kT, nullptr, sc,
            SEQ, SEQ, HDIM, HDIM, SEQ, (long)SEQ*HDIM, (long)HDIM*SEQ, scale);
    }

    // --- softmax over rows ---
    {
        int rows = BH*SEQ;                      // 151296 rows
        softmax_k<<<(rows + 7)/8, 256>>>(sc, rows);
    }

    // --- ctx = attn @ v   (batched, epilogue scatters to [tok, dim]) ---
    {
        dim3 grid((HDIM+63)/64, (SEQ+63)/64, BH);
        sgemm_k<64,64,16,4,4,3,0><<<grid, blk>>>(sc, v, nullptr, ctx,
            SEQ, HDIM, SEQ, SEQ, HDIM, (long)SEQ*SEQ, (long)SEQ*HDIM, one);
    }

    // --- attn_out = ctx @ Wo + bo ---
    {
        dim3 grid(DIM/128, (TOK + 127)/128);
        sgemm_k<128,128,16,8,8,0,0><<<grid, blk>>>(ctx, Wo, bo, ao, TOK, DIM, DIM, DIM, DIM, 0, 0, one);
    }

    // --- x1 = x + LN(attn_out) ---
    add_ln_k<<<TOK, 256>>>(x, ao, g1, be1, x1);

    // --- h = gelu(x1 @ W1 + b1) ---
    {
        dim3 grid(HID/128, (TOK + 127)/128);
        sgemm_k<128,128,16,8,8,0,1><<<grid, blk>>>(x1, W1, b1, hh, TOK, HID, DIM, DIM, HID, 0, 0, one);
    }

    // --- mlp = h @ W2 + b2 ---
    {
        dim3 grid(DIM/128, (TOK + 127)/128);
        sgemm_k<128,128,16,8,8,0,0><<<grid, blk>>>(hh, W2, b2, mlp, TOK, DIM, HID, HID, DIM, 0, 0, one);
    }

    // --- out = x1 + LN(mlp) ---
    add_ln_k<<<TOK, 256>>>(x1, mlp, g2, be2, out);
}

// round 2
// speedup vs baseline: 1.7214x; 1.7214x over previous
#include <cuda_runtime.h>
#include <cuda_bf16.h>
#include <mma.h>
#include <math.h>

using namespace nvcuda;

// ---------------- problem constants ----------------
#define BATCH   64
#define SEQ     197
#define TOK     (BATCH*SEQ)      // 12608
#define DIM     768
#define NHEAD   12
#define HDIM    64
#define HID     3072
#define BH      (BATCH*NHEAD)    // 768
#define LN_EPS  1e-6f

// ---------------- scratch (device globals; no allocation allowed) ----------------
__device__ float g_q  [(long)BH*SEQ*HDIM];   // [bh, s, d]
__device__ float g_kT [(long)BH*HDIM*SEQ];   // [bh, d, s]
__device__ float g_v  [(long)BH*SEQ*HDIM];   // [bh, s, d]
__device__ float g_sc [(long)BH*SEQ*SEQ];    // [bh, s, t]
__device__ float g_ctx[(long)TOK*DIM];       // [tok, dim]
__device__ float g_ao [(long)TOK*DIM];
__device__ float g_x1 [(long)TOK*DIM];
__device__ float g_h  [(long)TOK*HID];
__device__ float g_mlp[(long)TOK*DIM];

// ---------------- TF32 tensor-core GEMM ----------------
// C = alpha*(A[M,K] @ B[K,N]) + bias[n], optional GELU, multiple output layouts.
// OUTMODE: 0 plain [z,M,N]; 1 head-q/v [(b*H+h)*S+s, d]; 2 head-kT [(b*H+h)*HD+d, s];
//          3 ctx [(b*S+m)*DIM + h*HD + n]
// EPI: 0 none, 1 exact GELU
template<int BM,int BN,int BK,int WM,int WN,int OUTMODE,int EPI>
__launch_bounds__((BM/WM)*(BN/WN)*32)
__global__ void tgemm_k(const float* __restrict__ A, const float* __restrict__ Bw,
                        const float* __restrict__ bias, float* __restrict__ C,
                        int M, int N, int K, int lda, int ldb,
                        long strideA, long strideB, float alpha)
{
    constexpr int WARPS_M = BM/WM;
    constexpr int WARPS_N = BN/WN;
    constexpr int NWARP   = WARPS_M*WARPS_N;
    constexpr int THREADS = NWARP*32;
    constexpr int MI = WM/16;   // wmma tiles per warp in M
    constexpr int NI = WN/16;   // wmma tiles per warp in N
    constexpr int PADA = 4;
    constexpr int PADB = 4;

    __shared__ union {
        struct {
            float a[BM][BK+PADA];
            float b[BK][BN+PADB];
        } m;
        float stage[NWARP][16][20];
    } sm;

    const int z = blockIdx.z;
    A  += (long)z * strideA;
    Bw += (long)z * strideB;

    const int tileM = blockIdx.y * BM;
    const int tileN = blockIdx.x * BN;
    const int tid   = threadIdx.x;
    const int warpId= tid >> 5;
    const int lane  = tid & 31;
    const int wm    = warpId / WARPS_N;
    const int wn    = warpId % WARPS_N;

    wmma::fragment<wmma::accumulator, 16, 16, 8, float> acc[MI][NI];
    #pragma unroll
    for (int i=0;i<MI;i++)
        #pragma unroll
        for (int j=0;j<NI;j++) wmma::fill_fragment(acc[i][j], 0.0f);

    for (int k0 = 0; k0 < K; k0 += BK) {
        // load A tile [BM][BK] (row-major)
        #pragma unroll
        for (int idx = tid; idx < BM*BK; idx += THREADS) {
            int mm = idx / BK, kk = idx % BK;
            int gm = tileM + mm, gk = k0 + kk;
            sm.m.a[mm][kk] = (gm < M && gk < K) ? A[(long)gm*lda + gk] : 0.f;
        }
        // load B tile [BK][BN] (row-major)
        #pragma unroll
        for (int idx = tid; idx < BK*BN; idx += THREADS) {
            int kk = idx / BN, nn = idx % BN;
            int gk = k0 + kk, gn = tileN + nn;
            sm.m.b[kk][nn] = (gk < K && gn < N) ? Bw[(long)gk*ldb + gn] : 0.f;
        }
        __syncthreads();

        #pragma unroll
        for (int ks = 0; ks < BK/8; ks++) {
            wmma::fragment<wmma::matrix_a, 16, 16, 8, wmma::precision::tf32, wmma::row_major> af[MI];
            wmma::fragment<wmma::matrix_b, 16, 16, 8, wmma::precision::tf32, wmma::row_major> bf[NI];
            #pragma unroll
            for (int i=0;i<MI;i++) {
                wmma::load_matrix_sync(af[i], &sm.m.a[wm*WM + i*16][ks*8], BK+PADA);
                #pragma unroll
                for (int t=0;t<af[i].num_elements;t++)
                    af[i].x[t] = wmma::__float_to_tf32(af[i].x[t]);
            }
            #pragma unroll
            for (int j=0;j<NI;j++) {
                wmma::load_matrix_sync(bf[j], &sm.m.b[ks*8][wn*WN + j*16], BN+PADB);
                #pragma unroll
                for (int t=0;t<bf[j].num_elements;t++)
                    bf[j].x[t] = wmma::__float_to_tf32(bf[j].x[t]);
            }
            #pragma unroll
            for (int i=0;i<MI;i++)
                #pragma unroll
                for (int j=0;j<NI;j++)
                    wmma::mma_sync(acc[i][j], af[i], bf[j], acc[i][j]);
        }
        __syncthreads();
    }

    // epilogue: stage one 16x16 fragment at a time through smem
    const int r    = lane >> 1;         // 0..15 row within fragment
    const int cseg = (lane & 1) * 8;    // 0 or 8
    #pragma unroll
    for (int i=0;i<MI;i++) {
        #pragma unroll
        for (int j=0;j<NI;j++) {
            wmma::store_matrix_sync(&sm.stage[warpId][0][0], acc[i][j], 20, wmma::mem_row_major);
            __syncwarp();
            int gm = tileM + wm*WM + i*16 + r;
            if (gm < M) {
                int b = 0, s = 0;
                if (OUTMODE == 1 || OUTMODE == 2) { b = gm / SEQ; s = gm - b*SEQ; }
                #pragma unroll
                for (int t=0;t<8;t++) {
                    int gn = tileN + wn*WN + j*16 + cseg + t;
                    if (gn >= N) continue;
                    float val = sm.stage[warpId][r][cseg+t] * alpha;
                    if (bias) val += bias[gn];
                    if (EPI == 1) val = 0.5f * val * (1.f + erff(val * 0.70710678118654752f));
                    long idx;
                    if (OUTMODE == 0) {
                        idx = (long)z*M*N + (long)gm*N + gn;
                    } else if (OUTMODE == 1) {        // q/v
                        int h = gn >> 6, dd = gn & 63;
                        idx = (((long)(b*NHEAD + h))*SEQ + s)*HDIM + dd;
                    } else if (OUTMODE == 2) {        // kT
                        int h = gn >> 6, dd = gn & 63;
                        idx = (((long)(b*NHEAD + h))*HDIM + dd)*SEQ + s;
                    } else {                           // ctx
                        int bb = z / NHEAD, hh = z % NHEAD;
                        idx = ((long)(bb*SEQ + gm))*DIM + hh*HDIM + gn;
                    }
                    C[idx] = val;
                }
            }
            __syncwarp();
        }
    }
}

// ---------------- softmax: one warp per row of length 197 ----------------
__global__ void softmax_k(float* __restrict__ sc, int rows)
{
    int warp = (blockIdx.x * blockDim.x + threadIdx.x) >> 5;
    int lane = threadIdx.x & 31;
    if (warp >= rows) return;
    float* row = sc + (long)warp * SEQ;

    float v[7];
    float m = -1e30f;
    #pragma unroll
    for (int i=0;i<7;i++) {
        int c = lane + i*32;
        v[i] = (c < SEQ) ? row[c] : -1e30f;
        m = fmaxf(m, v[i]);
    }
    #pragma unroll
    for (int o=16;o;o>>=1) m = fmaxf(m, __shfl_xor_sync(0xffffffffu, m, o));

    float sum = 0.f;
    #pragma unroll
    for (int i=0;i<7;i++) { v[i] = __expf(v[i] - m); sum += v[i]; }
    #pragma unroll
    for (int o=16;o;o>>=1) sum += __shfl_xor_sync(0xffffffffu, sum, o);

    float inv = 1.f / sum;
    #pragma unroll
    for (int i=0;i<7;i++) {
        int c = lane + i*32;
        if (c < SEQ) row[c] = v[i]*inv;
    }
}

// ---------------- residual + LayerNorm: out = x + LN(y)*g + b ----------------
__global__ void add_ln_k(const float* __restrict__ x, const float* __restrict__ y,
                         const float* __restrict__ g, const float* __restrict__ be,
                         float* __restrict__ out)
{
    const int r = blockIdx.x;
    const float* yr = y + (long)r*DIM;
    const float* xr = x + (long)r*DIM;
    float* orow = out + (long)r*DIM;

    float s = 0.f, sq = 0.f;
    for (int i = threadIdx.x; i < DIM; i += blockDim.x) {
        float t = yr[i]; s += t; sq += t*t;
    }
    __shared__ float red[64];
    #pragma unroll
    for (int o=16;o;o>>=1) { s += __shfl_xor_sync(0xffffffffu, s, o); sq += __shfl_xor_sync(0xffffffffu, sq, o); }
    int w = threadIdx.x >> 5, lane = threadIdx.x & 31;
    if (lane == 0) { red[w] = s; red[w+32] = sq; }
    __syncthreads();
    if (threadIdx.x < 32) {
        int nw = blockDim.x >> 5;
        s  = (threadIdx.x < nw) ? red[threadIdx.x]      : 0.f;
        sq = (threadIdx.x < nw) ? red[threadIdx.x + 32] : 0.f;
        #pragma unroll
        for (int o=16;o;o>>=1) { s += __shfl_xor_sync(0xffffffffu, s, o); sq += __shfl_xor_sync(0xffffffffu, sq, o); }
        if (threadIdx.x == 0) { red[0] = s; red[1] = sq; }
    }
    __syncthreads();
    float mu   = red[0] * (1.f/DIM);
    float var  = red[1] * (1.f/DIM) - mu*mu;
    float rstd = rsqrtf(var + LN_EPS);
    for (int i = threadIdx.x; i < DIM; i += blockDim.x) {
        orow[i] = xr[i] + (yr[i] - mu) * rstd * g[i] + be[i];
    }
}

// ---------------- launch ----------------
extern "C" void kernel_launch(void* const* d_in, const int* in_sizes, int n_in,
                              void* d_out, int out_size)
{
    const float* x   = (const float*)d_in[0];
    const float* Wq  = (const float*)d_in[1];
    const float* bq  = (const float*)d_in[2];
    const float* Wk  = (const float*)d_in[3];
    const float* bk  = (const float*)d_in[4];
    const float* Wv  = (const float*)d_in[5];
    const float* bv  = (const float*)d_in[6];
    const float* Wo  = (const float*)d_in[7];
    const float* bo  = (const float*)d_in[8];
    const float* W1  = (const float*)d_in[9];
    const float* b1  = (const float*)d_in[10];
    const float* W2  = (const float*)d_in[11];
    const float* b2  = (const float*)d_in[12];
    const float* g1  = (const float*)d_in[13];
    const float* be1 = (const float*)d_in[14];
    const float* g2  = (const float*)d_in[15];
    const float* be2 = (const float*)d_in[16];
    float* out = (float*)d_out;

    float *q, *kT, *v, *sc, *ctx, *ao, *x1, *hh, *mlp;
    cudaGetSymbolAddress((void**)&q,   g_q);
    cudaGetSymbolAddress((void**)&kT,  g_kT);
    cudaGetSymbolAddress((void**)&v,   g_v);
    cudaGetSymbolAddress((void**)&sc,  g_sc);
    cudaGetSymbolAddress((void**)&ctx, g_ctx);
    cudaGetSymbolAddress((void**)&ao,  g_ao);
    cudaGetSymbolAddress((void**)&x1,  g_x1);
    cudaGetSymbolAddress((void**)&hh,  g_h);
    cudaGetSymbolAddress((void**)&mlp, g_mlp);

    const float one = 1.0f;
    const float scale = 0.125f;   // 1/sqrt(64)

    // big GEMM config: 128x128x32 tiles, 8 warps (64x32 warp tiles), 256 threads
    // small GEMM config: 64x64x32 tiles, 4 warps (32x32 warp tiles), 128 threads

    // --- QKV projections (fused head-layout epilogues) ---
    {
        dim3 grid(DIM/128, (TOK + 127)/128);
        tgemm_k<128,128,32,64,32,1,0><<<grid, 256>>>(x, Wq, bq, q,  TOK, DIM, DIM, DIM, DIM, 0, 0, one);
        tgemm_k<128,128,32,64,32,2,0><<<grid, 256>>>(x, Wk, bk, kT, TOK, DIM, DIM, DIM, DIM, 0, 0, one);
        tgemm_k<128,128,32,64,32,1,0><<<grid, 256>>>(x, Wv, bv, v,  TOK, DIM, DIM, DIM, DIM, 0, 0, one);
    }

    // --- scores = q @ kT * scale   (batched over 768 bh) ---
    {
        dim3 grid((SEQ+63)/64, (SEQ+63)/64, BH);
        tgemm_k<64,64,32,32,32,0,0><<<grid, 128>>>(q, kT, nullptr, sc,
            SEQ, SEQ, HDIM, HDIM, SEQ, (long)SEQ*HDIM, (long)HDIM*SEQ, scale);
    }

    // --- softmax over rows ---
    {
        int rows = BH*SEQ;                      // 151296 rows
        softmax_k<<<(rows + 7)/8, 256>>>(sc, rows);
    }

    // --- ctx = attn @ v   (batched, epilogue scatters to [tok, dim]) ---
    {
        dim3 grid((HDIM+63)/64, (SEQ+63)/64, BH);
        tgemm_k<64,64,32,32,32,3,0><<<grid, 128>>>(sc, v, nullptr, ctx,
            SEQ, HDIM, SEQ, SEQ, HDIM, (long)SEQ*SEQ, (long)SEQ*HDIM, one);
    }

    // --- attn_out = ctx @ Wo + bo ---
    {
        dim3 grid(DIM/128, (TOK + 127)/128);
        tgemm_k<128,128,32,64,32,0,0><<<grid, 256>>>(ctx, Wo, bo, ao, TOK, DIM, DIM, DIM, DIM, 0, 0, one);
    }

    // --- x1 = x + LN(attn_out) ---
    add_ln_k<<<TOK, 256>>>(x, ao, g1, be1, x1);

    // --- h = gelu(x1 @ W1 + b1) ---
    {
        dim3 grid(HID/128, (TOK + 127)/128);
        tgemm_k<128,128,32,64,32,0,1><<<grid, 256>>>(x1, W1, b1, hh, TOK, HID, DIM, DIM, HID, 0, 0, one);
    }

    // --- mlp = h @ W2 + b2 ---
    {
        dim3 grid(DIM/128, (TOK + 127)/128);
        tgemm_k<128,128,32,64,32,0,0><<<grid, 256>>>(hh, W2, b2, mlp, TOK, DIM, HID, HID, DIM, 0, 0, one);
    }

    // --- out = x1 + LN(mlp) ---
    add_ln_k<<<TOK, 256>>>(x1, mlp, g2, be2, out);
}

// round 3
// speedup vs baseline: 1.9054x; 1.1069x over previous
#include <cuda_runtime.h>
#include <cuda_bf16.h>
#include <mma.h>
#include <math.h>

using namespace nvcuda;

// ---------------- problem constants ----------------
#define BATCH   64
#define SEQ     197
#define TOK     (BATCH*SEQ)      // 12608
#define DIM     768
#define NHEAD   12
#define HDIM    64
#define HID     3072
#define BH      (BATCH*NHEAD)    // 768
#define LN_EPS  1e-6f

// padded attention dims
#define SEQP    208              // 13*16
#define KL      212              // SEQP+4  (row pitch for K^T and S)
#define VL      68               // HDIM+4

// ---------------- scratch (device globals) ----------------
__device__ float g_q  [(long)BH*SEQ*HDIM];   // [bh, s, d]
__device__ float g_k  [(long)BH*SEQ*HDIM];   // [bh, s, d]
__device__ float g_v  [(long)BH*SEQ*HDIM];   // [bh, s, d]
__device__ float g_ctx[(long)TOK*DIM];
__device__ float g_ao [(long)TOK*DIM];
__device__ float g_x1 [(long)TOK*DIM];
__device__ float g_h  [(long)TOK*HID];
__device__ float g_mlp[(long)TOK*DIM];

__device__ __forceinline__ float tf32r(float x) { return wmma::__float_to_tf32(x); }
__device__ __forceinline__ float gelu_exact(float v) {
    return 0.5f * v * (1.f + erff(v * 0.70710678118654752f));
}

// =====================================================================
// Big TF32 GEMM: C = A[M,K] @ B[K,N] + bias, optional GELU.
// BM=128,BN=128,BK=32, 256 threads (8 warps, 64x32 warp tiles).
// Double-buffered smem, register-staged prefetch, tf32 cvt at STS.
// OUTMODE: 0 plain [M,N];  1 head-split [(b*12+h)*197+s, d]
// Requires: K % 32 == 0, N % 128 == 0, lda=K, ldb=N.
// =====================================================================
#define GEMM_SMEM_BYTES ((2*128*36 + 2*32*132)*4)   // 70656; epilogue 128*132*4=67584 fits

template<int OUTMODE,int EPI>
__launch_bounds__(256)
__global__ void tgemm_k(const float* __restrict__ A, const float* __restrict__ Bw,
                        const float* __restrict__ bias, float* __restrict__ C,
                        int M, int N, int K)
{
    extern __shared__ float sm[];
    float* AsBase = sm;                    // [2][128][36]
    float* BsBase = sm + 2*128*36;         // [2][32][132]

    const int tileM = blockIdx.y * 128;
    const int tileN = blockIdx.x * 128;
    const int tid   = threadIdx.x;
    const int warpId= tid >> 5;
    const int wm    = warpId >> 2;         // 0..1
    const int wn    = warpId & 3;          // 0..3

    wmma::fragment<wmma::accumulator, 16, 16, 8, float> acc[4][2];
    #pragma unroll
    for (int i=0;i<4;i++)
        #pragma unroll
        for (int j=0;j<2;j++) wmma::fill_fragment(acc[i][j], 0.0f);

    float4 aReg[4], bReg[4];
    const int arow0 = tid >> 3, acol = (tid & 7) << 2;
    const int brow0 = tid >> 5, bcol = (tid & 31) << 2;

    // ---- prologue load k0=0 ----
    {
        #pragma unroll
        for (int p=0;p<4;p++) {
            int gm = tileM + p*32 + arow0;
            aReg[p] = (gm < M) ? *reinterpret_cast<const float4*>(&A[(size_t)gm*K + acol])
                               : make_float4(0.f,0.f,0.f,0.f);
        }
        #pragma unroll
        for (int p=0;p<4;p++) {
            int gk = p*8 + brow0;
            bReg[p] = *reinterpret_cast<const float4*>(&Bw[(size_t)gk*N + tileN + bcol]);
        }
        float* Ab = AsBase; float* Bb = BsBase;
        #pragma unroll
        for (int p=0;p<4;p++) {
            float4 v = aReg[p];
            v.x=tf32r(v.x); v.y=tf32r(v.y); v.z=tf32r(v.z); v.w=tf32r(v.w);
            *reinterpret_cast<float4*>(&Ab[(p*32 + arow0)*36 + acol]) = v;
        }
        #pragma unroll
        for (int p=0;p<4;p++) {
            float4 v = bReg[p];
            v.x=tf32r(v.x); v.y=tf32r(v.y); v.z=tf32r(v.z); v.w=tf32r(v.w);
            *reinterpret_cast<float4*>(&Bb[(p*8 + brow0)*132 + bcol]) = v;
        }
    }
    __syncthreads();

    int buf = 0;
    for (int k0 = 0; k0 < K; k0 += 32) {
        const bool hasNext = (k0 + 32) < K;
        if (hasNext) {
            #pragma unroll
            for (int p=0;p<4;p++) {
                int gm = tileM + p*32 + arow0;
                aReg[p] = (gm < M) ? *reinterpret_cast<const float4*>(&A[(size_t)gm*K + k0+32 + acol])
                                   : make_float4(0.f,0.f,0.f,0.f);
            }
            #pragma unroll
            for (int p=0;p<4;p++) {
                int gk = k0 + 32 + p*8 + brow0;
                bReg[p] = *reinterpret_cast<const float4*>(&Bw[(size_t)gk*N + tileN + bcol]);
            }
        }

        const float* Ab = AsBase + buf*128*36;
        const float* Bb = BsBase + buf*32*132;
        #pragma unroll
        for (int ks=0; ks<4; ks++) {
            wmma::fragment<wmma::matrix_a, 16, 16, 8, wmma::precision::tf32, wmma::row_major> af[4];
            wmma::fragment<wmma::matrix_b, 16, 16, 8, wmma::precision::tf32, wmma::row_major> bf[2];
            #pragma unroll
            for (int i=0;i<4;i++)
                wmma::load_matrix_sync(af[i], &Ab[(wm*64 + i*16)*36 + ks*8], 36);
            #pragma unroll
            for (int j=0;j<2;j++)
                wmma::load_matrix_sync(bf[j], &Bb[(ks*8)*132 + wn*32 + j*16], 132);
            #pragma unroll
            for (int i=0;i<4;i++)
                #pragma unroll
                for (int j=0;j<2;j++)
                    wmma::mma_sync(acc[i][j], af[i], bf[j], acc[i][j]);
        }

        if (hasNext) {
            float* Aw = AsBase + (buf^1)*128*36;
            float* Bww = BsBase + (buf^1)*32*132;
            #pragma unroll
            for (int p=0;p<4;p++) {
                float4 v = aReg[p];
                v.x=tf32r(v.x); v.y=tf32r(v.y); v.z=tf32r(v.z); v.w=tf32r(v.w);
                *reinterpret_cast<float4*>(&Aw[(p*32 + arow0)*36 + acol]) = v;
            }
            #pragma unroll
            for (int p=0;p<4;p++) {
                float4 v = bReg[p];
                v.x=tf32r(v.x); v.y=tf32r(v.y); v.z=tf32r(v.z); v.w=tf32r(v.w);
                *reinterpret_cast<float4*>(&Bww[(p*8 + brow0)*132 + bcol]) = v;
            }
        }
        __syncthreads();
        buf ^= 1;
    }

    // ---- epilogue: stage full 128x128 tile in smem, then coalesced writes ----
    #pragma unroll
    for (int i=0;i<4;i++)
        #pragma unroll
        for (int j=0;j<2;j++)
            wmma::store_matrix_sync(&sm[(wm*64 + i*16)*132 + wn*32 + j*16], acc[i][j], 132,
                                    wmma::mem_row_major);
    __syncthreads();

    const int row  = tid >> 1;
    const int half = tid & 1;
    const int gm   = tileM + row;
    if (gm < M) {
        int b = 0, s = 0;
        if (OUTMODE == 1) { b = gm / SEQ; s = gm - b*SEQ; }
        #pragma unroll
        for (int f=0; f<16; f++) {
            int c  = half*64 + f*4;
            int gn = tileN + c;
            float4 v = *reinterpret_cast<const float4*>(&sm[row*132 + c]);
            v.x += bias[gn];   v.y += bias[gn+1];
            v.z += bias[gn+2]; v.w += bias[gn+3];
            if (EPI == 1) {
                v.x = gelu_exact(v.x); v.y = gelu_exact(v.y);
                v.z = gelu_exact(v.z); v.w = gelu_exact(v.w);
            }
            if (OUTMODE == 0) {
                *reinterpret_cast<float4*>(&C[(size_t)gm*N + gn]) = v;
            } else {
                int h = gn >> 6, dd = gn & 63;
                size_t orow = ((size_t)(b*NHEAD + h)*SEQ + s);
                *reinterpret_cast<float4*>(&C[orow*HDIM + dd]) = v;
            }
        }
    }
}

// =====================================================================
// Fused attention: one CTA per (b,h). K^T,V resident in smem.
// 64-row Q tiles: S = (Q*scale) @ K^T -> softmax -> O = P @ V -> ctx.
// 256 threads (8 warps).
// =====================================================================
#define ATTN_SMEM_FLOATS (64*KL + SEQP*VL + 64*VL + 64*KL + 64*VL)
#define ATTN_SMEM_BYTES  (ATTN_SMEM_FLOATS*4)       // 199936 B

__launch_bounds__(256)
__global__ void attn_k(const float* __restrict__ q, const float* __restrict__ k,
                       const float* __restrict__ v, float* __restrict__ ctx)
{
    extern __shared__ float sm[];
    float* Ksm = sm;                    // [HDIM][KL]   K^T, cols >=197 zeroed
    float* Vsm = Ksm + 64*KL;           // [SEQP][VL]   rows >=197 zeroed
    float* Qsm = Vsm + SEQP*VL;         // [64][VL]
    float* Ssm = Qsm + 64*VL;           // [64][KL]
    float* Osm = Ssm + 64*KL;           // [64][VL]

    const int bh = blockIdx.x;
    const int b  = bh / NHEAD;
    const int h  = bh - b*NHEAD;
    const int tid = threadIdx.x;
    const int warpId = tid >> 5;
    const int lane   = tid & 31;
    const float scale = 0.125f;

    const float* qb = q + (size_t)bh*SEQ*HDIM;
    const float* kb = k + (size_t)bh*SEQ*HDIM;
    const float* vb = v + (size_t)bh*SEQ*HDIM;

    // ---- load K transposed: Ksm[d][s] = kb[s][d]; zero-pad s in [197,208) ----
    for (int idx = tid; idx < SEQP*HDIM; idx += 256) {
        int s = idx >> 6, d = idx & 63;
        float val = (s < SEQ) ? tf32r(kb[(size_t)s*HDIM + d]) : 0.f;
        Ksm[d*KL + s] = val;
    }
    // ---- load V: Vsm[t][dd]; zero-pad t in [197,208) ----
    for (int idx = tid; idx < SEQP*16; idx += 256) {
        int t = idx >> 4, f = idx & 15;
        float4 val;
        if (t < SEQ) {
            val = *reinterpret_cast<const float4*>(&vb[(size_t)t*HDIM + f*4]);
            val.x=tf32r(val.x); val.y=tf32r(val.y); val.z=tf32r(val.z); val.w=tf32r(val.w);
        } else val = make_float4(0.f,0.f,0.f,0.f);
        *reinterpret_cast<float4*>(&Vsm[t*VL + f*4]) = val;
    }
    __syncthreads();

    for (int s0 = 0; s0 < SEQ; s0 += 64) {
        // ---- Q tile (pre-scaled; scale is a power of 2 -> exact) ----
        for (int idx = tid; idx < 64*16; idx += 256) {
            int r = idx >> 4, f = idx & 15;
            int s = s0 + r;
            float4 val;
            if (s < SEQ) {
                val = *reinterpret_cast<const float4*>(&qb[(size_t)s*HDIM + f*4]);
                val.x=tf32r(val.x*scale); val.y=tf32r(val.y*scale);
                val.z=tf32r(val.z*scale); val.w=tf32r(val.w*scale);
            } else val = make_float4(0.f,0.f,0.f,0.f);
            *reinterpret_cast<float4*>(&Qsm[r*VL + f*4]) = val;
        }
        __syncthreads();

        // ---- scores: 4 m-tiles x 13 n-tiles = 52 warp tiles ----
        for (int t = warpId; t < 52; t += 8) {
            int mi = t / 13, ni = t - (t/13)*13;
            wmma::fragment<wmma::accumulator, 16, 16, 8, float> sac;
            wmma::fill_fragment(sac, 0.0f);
            #pragma unroll
            for (int ks=0; ks<8; ks++) {
                wmma::fragment<wmma::matrix_a, 16, 16, 8, wmma::precision::tf32, wmma::row_major> af;
                wmma::fragment<wmma::matrix_b, 16, 16, 8, wmma::precision::tf32, wmma::row_major> bf;
                wmma::load_matrix_sync(af, &Qsm[(mi*16)*VL + ks*8], VL);
                wmma::load_matrix_sync(bf, &Ksm[(ks*8)*KL + ni*16], KL);
                wmma::mma_sync(sac, af, bf, sac);
            }
            wmma::store_matrix_sync(&Ssm[(mi*16)*KL + ni*16], sac, KL, wmma::mem_row_major);
        }
        __syncthreads();

        // ---- softmax: each warp handles 8 rows ----
        #pragma unroll
        for (int rr = 0; rr < 8; rr++) {
            int r = warpId*8 + rr;
            float* rowp = &Ssm[r*KL];
            float x[7];
            float m = -1e30f;
            #pragma unroll
            for (int i=0;i<7;i++) {
                int c = lane + i*32;
                x[i] = (c < SEQ) ? rowp[c] : -1e30f;
                m = fmaxf(m, x[i]);
            }
            #pragma unroll
            for (int o=16;o;o>>=1) m = fmaxf(m, __shfl_xor_sync(0xffffffffu, m, o));
            float sum = 0.f;
            #pragma unroll
            for (int i=0;i<7;i++) { x[i] = __expf(x[i] - m); sum += x[i]; }
            #pragma unroll
            for (int o=16;o;o>>=1) sum += __shfl_xor_sync(0xffffffffu, sum, o);
            float inv = 1.f / sum;
            #pragma unroll
            for (int i=0;i<7;i++) {
                int c = lane + i*32;
                if (c < SEQ)       rowp[c] = tf32r(x[i]*inv);
                else if (c < SEQP) rowp[c] = 0.f;
            }
        }
        __syncthreads();

        // ---- O = P @ V: 4 m-tiles x 4 n-tiles = 16 warp tiles ----
        for (int t = warpId; t < 16; t += 8) {
            int mi = t >> 2, ni = t & 3;
            wmma::fragment<wmma::accumulator, 16, 16, 8, float> oac;
            wmma::fill_fragment(oac, 0.0f);
            #pragma unroll
            for (int ks=0; ks<26; ks++) {
                wmma::fragment<wmma::matrix_a, 16, 16, 8, wmma::precision::tf32, wmma::row_major> af;
                wmma::fragment<wmma::matrix_b, 16, 16, 8, wmma::precision::tf32, wmma::row_major> bf;
                wmma::load_matrix_sync(af, &Ssm[(mi*16)*KL + ks*8], KL);
                wmma::load_matrix_sync(bf, &Vsm[(ks*8)*VL + ni*16], VL);
                wmma::mma_sync(oac, af, bf, oac);
            }
            wmma::store_matrix_sync(&Osm[(mi*16)*VL + ni*16], oac, VL, wmma::mem_row_major);
        }
        __syncthreads();

        // ---- write ctx rows ----
        for (int idx = tid; idx < 64*16; idx += 256) {
            int r = idx >> 4, f = idx & 15;
            int s = s0 + r;
            if (s < SEQ) {
                float4 val = *reinterpret_cast<const float4*>(&Osm[r*VL + f*4]);
                *reinterpret_cast<float4*>(&ctx[((size_t)(b*SEQ + s))*DIM + h*HDIM + f*4]) = val;
            }
        }
        __syncthreads();
    }
}

// ---------------- residual + LayerNorm: out = x + LN(y)*g + b ----------------
__global__ void add_ln_k(const float* __restrict__ x, const float* __restrict__ y,
                         const float* __restrict__ g, const float* __restrict__ be,
                         float* __restrict__ out)
{
    const int r = blockIdx.x;
    const float* yr = y + (long)r*DIM;
    const float* xr = x + (long)r*DIM;
    float* orow = out + (long)r*DIM;

    float s = 0.f, sq = 0.f;
    for (int i = threadIdx.x; i < DIM; i += blockDim.x) {
        float t = yr[i]; s += t; sq += t*t;
    }
    __shared__ float red[64];
    #pragma unroll
    for (int o=16;o;o>>=1) { s += __shfl_xor_sync(0xffffffffu, s, o); sq += __shfl_xor_sync(0xffffffffu, sq, o); }
    int w = threadIdx.x >> 5, lane = threadIdx.x & 31;
    if (lane == 0) { red[w] = s; red[w+32] = sq; }
    __syncthreads();
    if (threadIdx.x < 32) {
        int nw = blockDim.x >> 5;
        s  = (threadIdx.x < nw) ? red[threadIdx.x]      : 0.f;
        sq = (threadIdx.x < nw) ? red[threadIdx.x + 32] : 0.f;
        #pragma unroll
        for (int o=16;o;o>>=1) { s += __shfl_xor_sync(0xffffffffu, s, o); sq += __shfl_xor_sync(0xffffffffu, sq, o); }
        if (threadIdx.x == 0) { red[0] = s; red[1] = sq; }
    }
    __syncthreads();
    float mu   = red[0] * (1.f/DIM);
    float var  = red[1] * (1.f/DIM) - mu*mu;
    float rstd = rsqrtf(var + LN_EPS);
    for (int i = threadIdx.x; i < DIM; i += blockDim.x) {
        orow[i] = xr[i] + (yr[i] - mu) * rstd * g[i] + be[i];
    }
}

// ---------------- launch ----------------
extern "C" void kernel_launch(void* const* d_in, const int* in_sizes, int n_in,
                              void* d_out, int out_size)
{
    const float* x   = (const float*)d_in[0];
    const float* Wq  = (const float*)d_in[1];
    const float* bq  = (const float*)d_in[2];
    const float* Wk  = (const float*)d_in[3];
    const float* bk  = (const float*)d_in[4];
    const float* Wv  = (const float*)d_in[5];
    const float* bv  = (const float*)d_in[6];
    const float* Wo  = (const float*)d_in[7];
    const float* bo  = (const float*)d_in[8];
    const float* W1  = (const float*)d_in[9];
    const float* b1  = (const float*)d_in[10];
    const float* W2  = (const float*)d_in[11];
    const float* b2  = (const float*)d_in[12];
    const float* g1  = (const float*)d_in[13];
    const float* be1 = (const float*)d_in[14];
    const float* g2  = (const float*)d_in[15];
    const float* be2 = (const float*)d_in[16];
    float* out = (float*)d_out;

    float *q, *k, *v, *ctx, *ao, *x1, *hh, *mlp;
    cudaGetSymbolAddress((void**)&q,   g_q);
    cudaGetSymbolAddress((void**)&k,   g_k);
    cudaGetSymbolAddress((void**)&v,   g_v);
    cudaGetSymbolAddress((void**)&ctx, g_ctx);
    cudaGetSymbolAddress((void**)&ao,  g_ao);
    cudaGetSymbolAddress((void**)&x1,  g_x1);
    cudaGetSymbolAddress((void**)&hh,  g_h);
    cudaGetSymbolAddress((void**)&mlp, g_mlp);

    cudaFuncSetAttribute(tgemm_k<0,0>, cudaFuncAttributeMaxDynamicSharedMemorySize, GEMM_SMEM_BYTES);
    cudaFuncSetAttribute(tgemm_k<1,0>, cudaFuncAttributeMaxDynamicSharedMemorySize, GEMM_SMEM_BYTES);
    cudaFuncSetAttribute(tgemm_k<0,1>, cudaFuncAttributeMaxDynamicSharedMemorySize, GEMM_SMEM_BYTES);
    cudaFuncSetAttribute(attn_k,       cudaFuncAttributeMaxDynamicSharedMemorySize, ATTN_SMEM_BYTES);

    const int mtiles = (TOK + 127)/128;   // 99

    // --- QKV projections into head-major layout ---
    {
        dim3 grid(DIM/128, mtiles);
        tgemm_k<1,0><<<grid, 256, GEMM_SMEM_BYTES>>>(x, Wq, bq, q, TOK, DIM, DIM);
        tgemm_k<1,0><<<grid, 256, GEMM_SMEM_BYTES>>>(x, Wk, bk, k, TOK, DIM, DIM);
        tgemm_k<1,0><<<grid, 256, GEMM_SMEM_BYTES>>>(x, Wv, bv, v, TOK, DIM, DIM);
    }

    // --- fused attention -> ctx [tok, dim] ---
    attn_k<<<BH, 256, ATTN_SMEM_BYTES>>>(q, k, v, ctx);

    // --- attn_out = ctx @ Wo + bo ---
    {
        dim3 grid(DIM/128, mtiles);
        tgemm_k<0,0><<<grid, 256, GEMM_SMEM_BYTES>>>(ctx, Wo, bo, ao, TOK, DIM, DIM);
    }

    // --- x1 = x + LN(attn_out) ---
    add_ln_k<<<TOK, 256>>>(x, ao, g1, be1, x1);

    // --- h = gelu(x1 @ W1 + b1) ---
    {
        dim3 grid(HID/128, mtiles);
        tgemm_k<0,1><<<grid, 256, GEMM_SMEM_BYTES>>>(x1, W1, b1, hh, TOK, HID, DIM);
    }

    // --- mlp = h @ W2 + b2 ---
    {
        dim3 grid(DIM/128, mtiles);
        tgemm_k<0,0><<<grid, 256, GEMM_SMEM_BYTES>>>(hh, W2, b2, mlp, TOK, DIM, HID);
    }

    // --- out = x1 + LN(mlp) ---
    add_ln_k<<<TOK, 256>>>(x1, mlp, g2, be2, out);
}

// round 4
// speedup vs baseline: 2.6357x; 1.3833x over previous
#include <cuda_runtime.h>
#include <cuda_bf16.h>
#include <mma.h>
#include <math.h>
#include <stdint.h>

using namespace nvcuda;

// ---------------- problem constants ----------------
#define BATCH   64
#define SEQ     197
#define TOK     (BATCH*SEQ)      // 12608
#define DIM     768
#define NHEAD   12
#define HDIM    64
#define HID     3072
#define BH      (BATCH*NHEAD)    // 768
#define LN_EPS  1e-6f

// padded attention dims
#define SEQP    208              // 13*16
#define KL      212              // SEQP+4
#define VL      68               // HDIM+4

// ---------------- scratch (device globals) ----------------
__device__ float g_q  [(long)BH*SEQ*HDIM];
__device__ float g_k  [(long)BH*SEQ*HDIM];
__device__ float g_v  [(long)BH*SEQ*HDIM];
__device__ float g_ctx[(long)TOK*DIM];
__device__ float g_ao [(long)TOK*DIM];
__device__ float g_x1 [(long)TOK*DIM];
__device__ float g_x1r[(long)TOK*DIM];
__device__ float g_xr [(long)TOK*DIM];
__device__ float g_h  [(long)TOK*HID];
__device__ float g_mlp[(long)TOK*DIM];
__device__ float g_wq [DIM*DIM];
__device__ float g_wk [DIM*DIM];
__device__ float g_wv [DIM*DIM];
__device__ float g_wo [DIM*DIM];
__device__ float g_w1 [DIM*HID];
__device__ float g_w2 [HID*DIM];

__device__ __forceinline__ float tf32r(float x) { return wmma::__float_to_tf32(x); }
__device__ __forceinline__ float gelu_exact(float v) {
    return 0.5f * v * (1.f + erff(v * 0.70710678118654752f));
}
__device__ __forceinline__ void cpa16(uint32_t dst, const float* src) {
    asm volatile("cp.async.cg.shared.global [%0], [%1], 16;" :: "r"(dst), "l"(src) : "memory");
}

// ---------------- tf32 RN rounding kernel (float4) ----------------
__global__ void round_k(const float* __restrict__ src, float* __restrict__ dst, int n4)
{
    int i = blockIdx.x*blockDim.x + threadIdx.x;
    if (i < n4) {
        float4 v = reinterpret_cast<const float4*>(src)[i];
        v.x = tf32r(v.x); v.y = tf32r(v.y); v.z = tf32r(v.z); v.w = tf32r(v.w);
        reinterpret_cast<float4*>(dst)[i] = v;
    }
}

// =====================================================================
// TF32 GEMM: C = epi((A[M,K]@B[K,N] + bias)*alpha)
// Inputs A,B must already be tf32-rounded. 256x128x32 tiles, 8 warps,
// 64x64 warp tiles, cp.async double buffering.
// OUTMODE: 0 plain [M,N]; 1 head-split [(b*12+h)*197+s, dd]
// EPI: 0 none, 1 exact GELU. ROUND: tf32-round output.
// Requires K%32==0, N%128==0.
// =====================================================================
#define GEMM_SMEM_BYTES (256*132*4)   // 135168 (epilogue stage dominates)

template<int OUTMODE,int EPI,int ROUND>
__launch_bounds__(256)
__global__ void tgemm_k(const float* __restrict__ A, const float* __restrict__ Bw,
                        const float* __restrict__ bias, float* __restrict__ C,
                        int M, int N, int K, float alpha)
{
    extern __shared__ float sm[];
    float* As = sm;                 // [2][256][36]
    float* Bs = sm + 2*256*36;      // [2][32][132]
    const uint32_t asBase = (uint32_t)__cvta_generic_to_shared(As);
    const uint32_t bsBase = (uint32_t)__cvta_generic_to_shared(Bs);

    const int tileM = blockIdx.y * 256;
    const int tileN = blockIdx.x * 128;
    const int tid   = threadIdx.x;
    const int warpId= tid >> 5;
    const int wm    = warpId >> 1;      // 0..3
    const int wn    = warpId & 1;       // 0..1

    const int aRow = tid >> 3;          // 0..31
    const int aCol = (tid & 7) << 2;    // 0..28
    const int bRow = tid >> 5;          // 0..7
    const int bCol = (tid & 31) << 2;   // 0..124

    const float* aPtr[8];
    #pragma unroll
    for (int t=0;t<8;t++) {
        int gm = tileM + t*32 + aRow;
        if (gm > M-1) gm = M-1;
        aPtr[t] = A + (size_t)gm*K + aCol;
    }
    const float* bPtr = Bw + (size_t)bRow*N + tileN + bCol;

    wmma::fragment<wmma::accumulator, 16, 16, 8, float> acc[4][4];
    #pragma unroll
    for (int i=0;i<4;i++)
        #pragma unroll
        for (int j=0;j<4;j++) wmma::fill_fragment(acc[i][j], 0.0f);

    auto loadTile = [&](int k0, int buf) {
        const uint32_t ab = asBase + (uint32_t)(buf*256*36)*4;
        const uint32_t bb = bsBase + (uint32_t)(buf*32*132)*4;
        #pragma unroll
        for (int t=0;t<8;t++)
            cpa16(ab + ((t*32 + aRow)*36 + aCol)*4, aPtr[t] + k0);
        #pragma unroll
        for (int t=0;t<4;t++)
            cpa16(bb + ((t*8 + bRow)*132 + bCol)*4, bPtr + (size_t)(k0 + t*8)*N);
        asm volatile("cp.async.commit_group;" ::: "memory");
    };

    const int NS = K >> 5;
    loadTile(0, 0);
    int buf = 0;
    for (int s = 0; s < NS; s++) {
        if (s+1 < NS) {
            loadTile((s+1) << 5, buf^1);
            asm volatile("cp.async.wait_group 1;" ::: "memory");
        } else {
            asm volatile("cp.async.wait_group 0;" ::: "memory");
        }
        __syncthreads();

        const float* Ab = As + buf*256*36 + (wm*64)*36;
        const float* Bb = Bs + buf*32*132 + wn*64;
        #pragma unroll
        for (int ks=0; ks<4; ks++) {
            wmma::fragment<wmma::matrix_a, 16, 16, 8, wmma::precision::tf32, wmma::row_major> af[4];
            wmma::fragment<wmma::matrix_b, 16, 16, 8, wmma::precision::tf32, wmma::row_major> bf[4];
            #pragma unroll
            for (int i=0;i<4;i++)
                wmma::load_matrix_sync(af[i], Ab + (i*16)*36 + ks*8, 36);
            #pragma unroll
            for (int j=0;j<4;j++)
                wmma::load_matrix_sync(bf[j], Bb + (ks*8)*132 + j*16, 132);
            #pragma unroll
            for (int i=0;i<4;i++)
                #pragma unroll
                for (int j=0;j<4;j++)
                    wmma::mma_sync(acc[i][j], af[i], bf[j], acc[i][j]);
        }
        __syncthreads();
        buf ^= 1;
    }

    // ---- epilogue: stage 256x128 tile in smem, coalesced float4 writes ----
    #pragma unroll
    for (int i=0;i<4;i++)
        #pragma unroll
        for (int j=0;j<4;j++)
            wmma::store_matrix_sync(&sm[(wm*64 + i*16)*132 + wn*64 + j*16], acc[i][j], 132,
                                    wmma::mem_row_major);
    __syncthreads();

    #pragma unroll
    for (int rr=0; rr<2; rr++) {
        const int row = rr*128 + (tid >> 1);
        const int gm  = tileM + row;
        if (gm >= M) continue;
        int b = 0, s = 0;
        if (OUTMODE == 1) { b = gm / SEQ; s = gm - b*SEQ; }
        #pragma unroll
        for (int f=0; f<16; f++) {
            int c  = (tid & 1)*64 + f*4;
            int gn = tileN + c;
            float4 v = *reinterpret_cast<const float4*>(&sm[row*132 + c]);
            v.x = (v.x + bias[gn  ]) * alpha;
            v.y = (v.y + bias[gn+1]) * alpha;
            v.z = (v.z + bias[gn+2]) * alpha;
            v.w = (v.w + bias[gn+3]) * alpha;
            if (EPI == 1) {
                v.x = gelu_exact(v.x); v.y = gelu_exact(v.y);
                v.z = gelu_exact(v.z); v.w = gelu_exact(v.w);
            }
            if (ROUND) {
                v.x = tf32r(v.x); v.y = tf32r(v.y); v.z = tf32r(v.z); v.w = tf32r(v.w);
            }
            if (OUTMODE == 0) {
                *reinterpret_cast<float4*>(&C[(size_t)gm*N + gn]) = v;
            } else {
                int h = gn >> 6, dd = gn & 63;
                size_t orow = (size_t)(b*NHEAD + h)*SEQ + s;
                *reinterpret_cast<float4*>(&C[orow*HDIM + dd]) = v;
            }
        }
    }
}

// =====================================================================
// Fused attention: one CTA per (b,h), 512 threads (16 warps).
// Inputs q (pre-scaled by 1/8), k, v already tf32-rounded.
// =====================================================================
#define ATTN_SMEM_FLOATS (64*KL + SEQP*VL + 64*VL + 64*KL)
#define ATTN_SMEM_BYTES  (ATTN_SMEM_FLOATS*4)   // 182528

__launch_bounds__(512)
__global__ void attn_k(const float* __restrict__ q, const float* __restrict__ k,
                       const float* __restrict__ v, float* __restrict__ ctx)
{
    extern __shared__ float sm[];
    float* Ksm = sm;                    // [HDIM][KL]  K^T
    float* Vsm = Ksm + 64*KL;           // [SEQP][VL]
    float* QO  = Vsm + SEQP*VL;         // [64][VL]   Q tile, reused for O
    float* Ssm = QO  + 64*VL;           // [64][KL]

    const int bh = blockIdx.x;
    const int b  = bh / NHEAD;
    const int h  = bh - b*NHEAD;
    const int tid    = threadIdx.x;
    const int warpId = tid >> 5;        // 0..15
    const int lane   = tid & 31;

    const float* qb = q + (size_t)bh*SEQ*HDIM;
    const float* kb = k + (size_t)bh*SEQ*HDIM;
    const float* vb = v + (size_t)bh*SEQ*HDIM;

    // K^T: Ksm[d][s], zero-pad s>=197
    for (int idx = tid; idx < SEQP*HDIM; idx += 512) {
        int s = idx >> 6, d = idx & 63;
        Ksm[d*KL + s] = (s < SEQ) ? kb[(size_t)s*HDIM + d] : 0.f;
    }
    // V: Vsm[t][dd], zero-pad t>=197
    for (int idx = tid; idx < SEQP*16; idx += 512) {
        int t = idx >> 4, f = idx & 15;
        float4 val = (t < SEQ) ? *reinterpret_cast<const float4*>(&vb[(size_t)t*HDIM + f*4])
                               : make_float4(0.f,0.f,0.f,0.f);
        *reinterpret_cast<float4*>(&Vsm[t*VL + f*4]) = val;
    }
    __syncthreads();

    for (int s0 = 0; s0 < SEQ; s0 += 64) {
        // Q tile (already scaled+rounded at projection)
        for (int idx = tid; idx < 64*16; idx += 512) {
            int r = idx >> 4, f = idx & 15;
            int s = s0 + r;
            float4 val = (s < SEQ) ? *reinterpret_cast<const float4*>(&qb[(size_t)s*HDIM + f*4])
                                   : make_float4(0.f,0.f,0.f,0.f);
            *reinterpret_cast<float4*>(&QO[r*VL + f*4]) = val;
        }
        __syncthreads();

        // scores: 4 x 13 = 52 warp tiles over 16 warps
        for (int t = warpId; t < 52; t += 16) {
            int mi = t / 13, ni = t - (t/13)*13;
            wmma::fragment<wmma::accumulator, 16, 16, 8, float> sac;
            wmma::fill_fragment(sac, 0.0f);
            #pragma unroll
            for (int ks=0; ks<8; ks++) {
                wmma::fragment<wmma::matrix_a, 16, 16, 8, wmma::precision::tf32, wmma::row_major> af;
                wmma::fragment<wmma::matrix_b, 16, 16, 8, wmma::precision::tf32, wmma::row_major> bf;
                wmma::load_matrix_sync(af, &QO[(mi*16)*VL + ks*8], VL);
                wmma::load_matrix_sync(bf, &Ksm[(ks*8)*KL + ni*16], KL);
                wmma::mma_sync(sac, af, bf, sac);
            }
            wmma::store_matrix_sync(&Ssm[(mi*16)*KL + ni*16], sac, KL, wmma::mem_row_major);
        }
        __syncthreads();

        // softmax: 4 rows per warp
        #pragma unroll
        for (int rr = 0; rr < 4; rr++) {
            int r = warpId*4 + rr;
            float* rowp = &Ssm[r*KL];
            float x[7];
            float m = -1e30f;
            #pragma unroll
            for (int i=0;i<7;i++) {
                int c = lane + i*32;
                x[i] = (c < SEQ) ? rowp[c] : -1e30f;
                m = fmaxf(m, x[i]);
            }
            #pragma unroll
            for (int o=16;o;o>>=1) m = fmaxf(m, __shfl_xor_sync(0xffffffffu, m, o));
            float sum = 0.f;
            #pragma unroll
            for (int i=0;i<7;i++) { x[i] = __expf(x[i] - m); sum += x[i]; }
            #pragma unroll
            for (int o=16;o;o>>=1) sum += __shfl_xor_sync(0xffffffffu, sum, o);
            float inv = 1.f / sum;
            #pragma unroll
            for (int i=0;i<7;i++) {
                int c = lane + i*32;
                if (c < SEQ)       rowp[c] = tf32r(x[i]*inv);
                else if (c < SEQP) rowp[c] = 0.f;
            }
        }
        __syncthreads();

        // O = P @ V: 16 warp tiles, one per warp
        {
            int mi = warpId >> 2, ni = warpId & 3;
            wmma::fragment<wmma::accumulator, 16, 16, 8, float> oac;
            wmma::fill_fragment(oac, 0.0f);
            #pragma unroll
            for (int ks=0; ks<26; ks++) {
                wmma::fragment<wmma::matrix_a, 16, 16, 8, wmma::precision::tf32, wmma::row_major> af;
                wmma::fragment<wmma::matrix_b, 16, 16, 8, wmma::precision::tf32, wmma::row_major> bf;
                wmma::load_matrix_sync(af, &Ssm[(mi*16)*KL + ks*8], KL);
                wmma::load_matrix_sync(bf, &Vsm[(ks*8)*VL + ni*16], VL);
                wmma::mma_sync(oac, af, bf, oac);
            }
            wmma::store_matrix_sync(&QO[(mi*16)*VL + ni*16], oac, VL, wmma::mem_row_major);
        }
        __syncthreads();

        // write ctx rows (tf32-rounded: ctx feeds Wo GEMM)
        for (int idx = tid; idx < 64*16; idx += 512) {
            int r = idx >> 4, f = idx & 15;
            int s = s0 + r;
            if (s < SEQ) {
                float4 val = *reinterpret_cast<const float4*>(&QO[r*VL + f*4]);
                val.x=tf32r(val.x); val.y=tf32r(val.y); val.z=tf32r(val.z); val.w=tf32r(val.w);
                *reinterpret_cast<float4*>(&ctx[((size_t)(b*SEQ + s))*DIM + h*HDIM + f*4]) = val;
            }
        }
        __syncthreads();
    }
}

// ---------------- residual + LayerNorm (optional rounded copy) ----------------
__global__ void add_ln_k(const float* __restrict__ x, const float* __restrict__ y,
                         const float* __restrict__ g, const float* __restrict__ be,
                         float* __restrict__ out, float* __restrict__ outR)
{
    const int r = blockIdx.x;
    const float* yr = y + (long)r*DIM;
    const float* xr = x + (long)r*DIM;

    float s = 0.f, sq = 0.f;
    for (int i = threadIdx.x; i < DIM; i += blockDim.x) {
        float t = yr[i]; s += t; sq += t*t;
    }
    __shared__ float red[64];
    #pragma unroll
    for (int o=16;o;o>>=1) { s += __shfl_xor_sync(0xffffffffu, s, o); sq += __shfl_xor_sync(0xffffffffu, sq, o); }
    int w = threadIdx.x >> 5, lane = threadIdx.x & 31;
    if (lane == 0) { red[w] = s; red[w+32] = sq; }
    __syncthreads();
    if (threadIdx.x < 32) {
        int nw = blockDim.x >> 5;
        s  = (threadIdx.x < nw) ? red[threadIdx.x]      : 0.f;
        sq = (threadIdx.x < nw) ? red[threadIdx.x + 32] : 0.f;
        #pragma unroll
        for (int o=16;o;o>>=1) { s += __shfl_xor_sync(0xffffffffu, s, o); sq += __shfl_xor_sync(0xffffffffu, sq, o); }
        if (threadIdx.x == 0) { red[0] = s; red[1] = sq; }
    }
    __syncthreads();
    float mu   = red[0] * (1.f/DIM);
    float var  = red[1] * (1.f/DIM) - mu*mu;
    float rstd = rsqrtf(var + LN_EPS);
    for (int i = threadIdx.x; i < DIM; i += blockDim.x) {
        float val = xr[i] + (yr[i] - mu) * rstd * g[i] + be[i];
        out[(long)r*DIM + i] = val;
        if (outR) outR[(long)r*DIM + i] = tf32r(val);
    }
}

// ---------------- launch ----------------
extern "C" void kernel_launch(void* const* d_in, const int* in_sizes, int n_in,
                              void* d_out, int out_size)
{
    const float* x   = (const float*)d_in[0];
    const float* Wq  = (const float*)d_in[1];
    const float* bq  = (const float*)d_in[2];
    const float* Wk  = (const float*)d_in[3];
    const float* bk  = (const float*)d_in[4];
    const float* Wv  = (const float*)d_in[5];
    const float* bv  = (const float*)d_in[6];
    const float* Wo  = (const float*)d_in[7];
    const float* bo  = (const float*)d_in[8];
    const float* W1  = (const float*)d_in[9];
    const float* b1  = (const float*)d_in[10];
    const float* W2  = (const float*)d_in[11];
    const float* b2  = (const float*)d_in[12];
    const float* g1  = (const float*)d_in[13];
    const float* be1 = (const float*)d_in[14];
    const float* g2  = (const float*)d_in[15];
    const float* be2 = (const float*)d_in[16];
    float* out = (float*)d_out;

    float *q,*k,*v,*ctx,*ao,*x1,*x1r,*xr,*hh,*mlp,*wq,*wk,*wv,*wo,*w1,*w2;
    cudaGetSymbolAddress((void**)&q,   g_q);
    cudaGetSymbolAddress((void**)&k,   g_k);
    cudaGetSymbolAddress((void**)&v,   g_v);
    cudaGetSymbolAddress((void**)&ctx, g_ctx);
    cudaGetSymbolAddress((void**)&ao,  g_ao);
    cudaGetSymbolAddress((void**)&x1,  g_x1);
    cudaGetSymbolAddress((void**)&x1r, g_x1r);
    cudaGetSymbolAddress((void**)&xr,  g_xr);
    cudaGetSymbolAddress((void**)&hh,  g_h);
    cudaGetSymbolAddress((void**)&mlp, g_mlp);
    cudaGetSymbolAddress((void**)&wq,  g_wq);
    cudaGetSymbolAddress((void**)&wk,  g_wk);
    cudaGetSymbolAddress((void**)&wv,  g_wv);
    cudaGetSymbolAddress((void**)&wo,  g_wo);
    cudaGetSymbolAddress((void**)&w1,  g_w1);
    cudaGetSymbolAddress((void**)&w2,  g_w2);

    cudaFuncSetAttribute(tgemm_k<1,0,1>, cudaFuncAttributeMaxDynamicSharedMemorySize, GEMM_SMEM_BYTES);
    cudaFuncSetAttribute(tgemm_k<0,0,0>, cudaFuncAttributeMaxDynamicSharedMemorySize, GEMM_SMEM_BYTES);
    cudaFuncSetAttribute(tgemm_k<0,1,1>, cudaFuncAttributeMaxDynamicSharedMemorySize, GEMM_SMEM_BYTES);
    cudaFuncSetAttribute(attn_k,         cudaFuncAttributeMaxDynamicSharedMemorySize, ATTN_SMEM_BYTES);

    // --- tf32-round weights + x ---
    {
        const int T = 256;
        int n;
        n = DIM*DIM/4;   round_k<<<(n+T-1)/T, T>>>(Wq, wq, n);
        n = DIM*DIM/4;   round_k<<<(n+T-1)/T, T>>>(Wk, wk, n);
        n = DIM*DIM/4;   round_k<<<(n+T-1)/T, T>>>(Wv, wv, n);
        n = DIM*DIM/4;   round_k<<<(n+T-1)/T, T>>>(Wo, wo, n);
        n = DIM*HID/4;   round_k<<<(n+T-1)/T, T>>>(W1, w1, n);
        n = HID*DIM/4;   round_k<<<(n+T-1)/T, T>>>(W2, w2, n);
        n = TOK*DIM/4;   round_k<<<(n+T-1)/T, T>>>(x,  xr, n);
    }

    const int mtiles = (TOK + 255)/256;   // 50

    // --- QKV projections (head-major, rounded; q pre-scaled by 1/8) ---
    {
        dim3 grid(DIM/128, mtiles);
        tgemm_k<1,0,1><<<grid, 256, GEMM_SMEM_BYTES>>>(xr, wq, bq, q, TOK, DIM, DIM, 0.125f);
        tgemm_k<1,0,1><<<grid, 256, GEMM_SMEM_BYTES>>>(xr, wk, bk, k, TOK, DIM, DIM, 1.0f);
        tgemm_k<1,0,1><<<grid, 256, GEMM_SMEM_BYTES>>>(xr, wv, bv, v, TOK, DIM, DIM, 1.0f);
    }

    // --- fused attention -> ctx (rounded) ---
    attn_k<<<BH, 512, ATTN_SMEM_BYTES>>>(q, k, v, ctx);

    // --- attn_out = ctx @ Wo + bo ---
    {
        dim3 grid(DIM/128, mtiles);
        tgemm_k<0,0,0><<<grid, 256, GEMM_SMEM_BYTES>>>(ctx, wo, bo, ao, TOK, DIM, DIM, 1.0f);
    }

    // --- x1 = x + LN(attn_out); also rounded copy for MLP1 ---
    add_ln_k<<<TOK, 256>>>(x, ao, g1, be1, x1, x1r);

    // --- h = gelu(x1 @ W1 + b1) (rounded) ---
    {
        dim3 grid(HID/128, mtiles);
        tgemm_k<0,1,1><<<grid, 256, GEMM_SMEM_BYTES>>>(x1r, w1, b1, hh, TOK, HID, DIM, 1.0f);
    }

    // --- mlp = h @ W2 + b2 ---
    {
        dim3 grid(DIM/128, mtiles);
        tgemm_k<0,0,0><<<grid, 256, GEMM_SMEM_BYTES>>>(hh, w2, b2, mlp, TOK, DIM, HID, 1.0f);
    }

    // --- out = x1 + LN(mlp) ---
    add_ln_k<<<TOK, 256>>>(x1, mlp, g2, be2, out, nullptr);
}